// round 11
// baseline (speedup 1.0000x reference)
#include <cuda_runtime.h>

#define IN_F   64
#define OUT_F  100
#define MAX_NODES 100000
#define CAP    128   // per-node edge bucket capacity (deg ~ Binom, mean 16, sigma 4)

// Scratch (allocation-free rule: device globals)
__device__ int   g_cnt[MAX_NODES];                     // per-node edge count
__device__ int   g_eidx[(size_t)MAX_NODES * CAP];      // per-node edge buckets
__device__ float g_S[(size_t)MAX_NODES * IN_F];        // segment sums

// ---------------------------------------------------------------------------
// 1. zero counts
// ---------------------------------------------------------------------------
__global__ void zero_cnt_kernel(int n_nodes) {
    int i = blockIdx.x * blockDim.x + threadIdx.x;
    if (i < n_nodes) g_cnt[i] = 0;
}

// ---------------------------------------------------------------------------
// 2. bucket fill: int4 dst reads, 4 edges per thread.
// ---------------------------------------------------------------------------
__global__ void fill_kernel(const int4* __restrict__ dst4, int n_edges) {
    int i = blockIdx.x * blockDim.x + threadIdx.x;
    int e0 = i * 4;
    if (e0 + 4 <= n_edges) {
        int4 d = __ldg(dst4 + i);
        int p0 = atomicAdd(&g_cnt[d.x], 1);
        int p1 = atomicAdd(&g_cnt[d.y], 1);
        int p2 = atomicAdd(&g_cnt[d.z], 1);
        int p3 = atomicAdd(&g_cnt[d.w], 1);
        if (p0 < CAP) g_eidx[(size_t)d.x * CAP + p0] = e0;
        if (p1 < CAP) g_eidx[(size_t)d.y * CAP + p1] = e0 + 1;
        if (p2 < CAP) g_eidx[(size_t)d.z * CAP + p2] = e0 + 2;
        if (p3 < CAP) g_eidx[(size_t)d.w * CAP + p3] = e0 + 3;
    } else if (e0 < n_edges) {
        const int* dst = (const int*)dst4;
        for (int e = e0; e < n_edges; e++) {
            int d = __ldg(dst + e);
            int p = atomicAdd(&g_cnt[d], 1);
            if (p < CAP) g_eidx[(size_t)d * CAP + p] = e;
        }
    }
}

// ---------------------------------------------------------------------------
// 3. gather: one warp per node. float4 lanes -> 16 lanes cover one 256B row,
//    warp LDG.128 fetches TWO edge rows. 16-edge main batches + 8/4/2/1
//    cascade (no data-dependent remainder chain).
// ---------------------------------------------------------------------------
__global__ __launch_bounds__(128)
void gather_kernel(const float4* __restrict__ e4, int n_nodes) {
    int w    = (blockIdx.x * blockDim.x + threadIdx.x) >> 5;
    int lane = threadIdx.x & 31;
    if (w >= n_nodes) return;

    int deg  = g_cnt[w];
    const int* base = g_eidx + (size_t)w * CAP;
    int half = lane >> 4;
    int l16  = lane & 15;

    float ax = 0.f, ay = 0.f, az = 0.f, aw = 0.f;
    int j = 0;
    for (; j + 16 <= deg; j += 16) {
        int e0 = __ldg(base + j + 0  + half);
        int e1 = __ldg(base + j + 2  + half);
        int e2 = __ldg(base + j + 4  + half);
        int e3 = __ldg(base + j + 6  + half);
        int e4i = __ldg(base + j + 8  + half);
        int e5 = __ldg(base + j + 10 + half);
        int e6 = __ldg(base + j + 12 + half);
        int e7 = __ldg(base + j + 14 + half);
        float4 v0 = e4[(size_t)e0 * 16 + l16];
        float4 v1 = e4[(size_t)e1 * 16 + l16];
        float4 v2 = e4[(size_t)e2 * 16 + l16];
        float4 v3 = e4[(size_t)e3 * 16 + l16];
        float4 v4 = e4[(size_t)e4i * 16 + l16];
        float4 v5 = e4[(size_t)e5 * 16 + l16];
        float4 v6 = e4[(size_t)e6 * 16 + l16];
        float4 v7 = e4[(size_t)e7 * 16 + l16];
        ax += ((v0.x + v1.x) + (v2.x + v3.x)) + ((v4.x + v5.x) + (v6.x + v7.x));
        ay += ((v0.y + v1.y) + (v2.y + v3.y)) + ((v4.y + v5.y) + (v6.y + v7.y));
        az += ((v0.z + v1.z) + (v2.z + v3.z)) + ((v4.z + v5.z) + (v6.z + v7.z));
        aw += ((v0.w + v1.w) + (v2.w + v3.w)) + ((v4.w + v5.w) + (v6.w + v7.w));
    }
    if (j + 8 <= deg) {
        int e0 = __ldg(base + j + 0 + half);
        int e1 = __ldg(base + j + 2 + half);
        int e2 = __ldg(base + j + 4 + half);
        int e3 = __ldg(base + j + 6 + half);
        float4 v0 = e4[(size_t)e0 * 16 + l16];
        float4 v1 = e4[(size_t)e1 * 16 + l16];
        float4 v2 = e4[(size_t)e2 * 16 + l16];
        float4 v3 = e4[(size_t)e3 * 16 + l16];
        ax += (v0.x + v1.x) + (v2.x + v3.x);
        ay += (v0.y + v1.y) + (v2.y + v3.y);
        az += (v0.z + v1.z) + (v2.z + v3.z);
        aw += (v0.w + v1.w) + (v2.w + v3.w);
        j += 8;
    }
    if (j + 4 <= deg) {
        int e0 = __ldg(base + j + 0 + half);
        int e1 = __ldg(base + j + 2 + half);
        float4 v0 = e4[(size_t)e0 * 16 + l16];
        float4 v1 = e4[(size_t)e1 * 16 + l16];
        ax += v0.x + v1.x;
        ay += v0.y + v1.y;
        az += v0.z + v1.z;
        aw += v0.w + v1.w;
        j += 4;
    }
    if (j + 2 <= deg) {
        int e0 = __ldg(base + j + half);
        float4 v = e4[(size_t)e0 * 16 + l16];
        ax += v.x; ay += v.y; az += v.z; aw += v.w;
        j += 2;
    }
    if (j < deg && half == 0) {
        int e0 = __ldg(base + j);
        float4 v = e4[(size_t)e0 * 16 + l16];
        ax += v.x; ay += v.y; az += v.z; aw += v.w;
    }

    ax += __shfl_xor_sync(0xffffffffu, ax, 16);
    ay += __shfl_xor_sync(0xffffffffu, ay, 16);
    az += __shfl_xor_sync(0xffffffffu, az, 16);
    aw += __shfl_xor_sync(0xffffffffu, aw, 16);

    if (half == 0)
        reinterpret_cast<float4*>(g_S)[(size_t)w * 16 + l16] =
            make_float4(ax, ay, az, aw);
}

// ---------------------------------------------------------------------------
// 4. GEMM: NT=128 nodes/block, 320 threads (10 warps), 3 blocks/SM pinned.
//    Wsm amortized over 2x nodes -> 30 warps/SM (was 25). Dynamic smem.
//    Per-thread shape unchanged: 8 nodes x 5 outs, scalar LDS (proven form).
// ---------------------------------------------------------------------------
#define NT   128
#define NG   16
#define OG   20
#define TPB  (NG * OG)   // 320
#define SS   65          // padded Ssm row stride

// dynamic smem layout (floats):
//   Ssm [NT*SS]          8320
//   Wsm [IN_F*OUT_F]     6400
//   bsm [OUT_F]           100
//   invd[NT]              128
//   bfac[NT]              128
#define SMEM_FLOATS (NT * SS + IN_F * OUT_F + OUT_F + NT + NT)

__global__ __launch_bounds__(TPB, 3)
void gemm_kernel(const float* __restrict__ W,
                 const float* __restrict__ b,
                 float* __restrict__ out,
                 int n_nodes) {
    extern __shared__ float smem[];
    float* Ssm  = smem;
    float* Wsm  = Ssm + NT * SS;
    float* bsm  = Wsm + IN_F * OUT_F;
    float* invd = bsm + OUT_F;
    float* bfac = invd + NT;

    int tid   = threadIdx.x;
    int node0 = blockIdx.x * NT;

    for (int i = tid; i < IN_F * OUT_F; i += TPB) {
        int o = i / IN_F, k = i % IN_F;
        Wsm[k * OUT_F + o] = W[i];
    }
    for (int i = tid; i < OUT_F; i += TPB) bsm[i] = b[i];

    for (int i = tid; i < NT * 16; i += TPB) {
        int r = i >> 4, c = i & 15;
        int node = node0 + r;
        float4 v = make_float4(0.f, 0.f, 0.f, 0.f);
        if (node < n_nodes)
            v = reinterpret_cast<const float4*>(g_S)[(size_t)node * 16 + c];
        float* p = &Ssm[r * SS + c * 4];
        p[0] = v.x; p[1] = v.y; p[2] = v.z; p[3] = v.w;
    }

    for (int i = tid; i < NT; i += TPB) {
        int node = node0 + i;
        int dg = (node < n_nodes) ? g_cnt[node] : 0;
        invd[i] = (dg > 0) ? (1.0f / (float)dg) : 0.0f;
        bfac[i] = (dg > 0) ? 1.0f : 0.0f;
    }
    __syncthreads();

    int og = tid % OG;   // outs [og*5, og*5+5)
    int ng = tid / OG;   // nodes [ng*8, ng*8+8)

    float acc[8][5];
#pragma unroll
    for (int j = 0; j < 8; j++)
#pragma unroll
        for (int i = 0; i < 5; i++) acc[j][i] = 0.0f;

    const float* wp = &Wsm[og * 5];
    const float* sp = &Ssm[ng * 8 * SS];

#pragma unroll 4
    for (int k = 0; k < IN_F; k++) {
        float w0 = wp[k * OUT_F + 0];
        float w1 = wp[k * OUT_F + 1];
        float w2 = wp[k * OUT_F + 2];
        float w3 = wp[k * OUT_F + 3];
        float w4 = wp[k * OUT_F + 4];
#pragma unroll
        for (int j = 0; j < 8; j++) {
            float s = sp[j * SS + k];
            acc[j][0] += s * w0;
            acc[j][1] += s * w1;
            acc[j][2] += s * w2;
            acc[j][3] += s * w3;
            acc[j][4] += s * w4;
        }
    }

#pragma unroll
    for (int j = 0; j < 8; j++) {
        int lr   = ng * 8 + j;
        int node = node0 + lr;
        if (node >= n_nodes) continue;
        float inv = invd[lr];
        float bf  = bfac[lr];
        float* op = out + (size_t)node * OUT_F + og * 5;
#pragma unroll
        for (int i = 0; i < 5; i++)
            op[i] = acc[j][i] * inv + bsm[og * 5 + i] * bf;
    }
}

// ---------------------------------------------------------------------------
extern "C" void kernel_launch(void* const* d_in, const int* in_sizes, int n_in,
                              void* d_out, int out_size) {
    const float* e   = (const float*)d_in[0];
    const int*   dst = (const int*)d_in[1];
    const float* W   = (const float*)d_in[2];
    const float* b   = (const float*)d_in[3];
    float*       out = (float*)d_out;

    int n_edges = in_sizes[1];
    int n_nodes = out_size / OUT_F;

    // opt-in for >48KB dynamic smem (immediate host call, no allocation)
    cudaFuncSetAttribute(gemm_kernel,
                         cudaFuncAttributeMaxDynamicSharedMemorySize,
                         SMEM_FLOATS * (int)sizeof(float));

    zero_cnt_kernel<<<(n_nodes + 255) / 256, 256>>>(n_nodes);
    int fthreads = (n_edges + 3) / 4;
    fill_kernel<<<(fthreads + 255) / 256, 256>>>((const int4*)dst, n_edges);
    gather_kernel<<<(n_nodes * 32 + 127) / 128, 128>>>((const float4*)e, n_nodes);
    gemm_kernel<<<(n_nodes + NT - 1) / NT, TPB,
                  SMEM_FLOATS * sizeof(float)>>>(W, b, out, n_nodes);
}

// round 12
// speedup vs baseline: 1.1057x; 1.1057x over previous
#include <cuda_runtime.h>

#define IN_F   64
#define OUT_F  100
#define MAX_NODES 100000
#define CAP    128   // per-node edge bucket capacity (deg ~ Binom, mean 16, sigma 4)

// Scratch (allocation-free rule: device globals)
__device__ int   g_cnt[MAX_NODES];                     // per-node edge count
__device__ int   g_eidx[(size_t)MAX_NODES * CAP];      // per-node edge buckets
__device__ float g_S[(size_t)MAX_NODES * IN_F];        // segment sums

// ---------------------------------------------------------------------------
// packed f32x2 helpers (sm_103a: FFMA2 only reachable via PTX)
// ---------------------------------------------------------------------------
__device__ __forceinline__ void fma2(unsigned long long& d,
                                     unsigned long long a,
                                     unsigned long long b) {
    asm("fma.rn.f32x2 %0, %1, %2, %0;" : "+l"(d) : "l"(a), "l"(b));
}
__device__ __forceinline__ unsigned long long dup2(float x) {
    unsigned long long r;
    asm("mov.b64 %0, {%1, %1};" : "=l"(r) : "f"(x));
    return r;
}
__device__ __forceinline__ void unpack2(float& lo, float& hi, unsigned long long v) {
    asm("mov.b64 {%0, %1}, %2;" : "=f"(lo), "=f"(hi) : "l"(v));
}

// ---------------------------------------------------------------------------
// 1. zero counts
// ---------------------------------------------------------------------------
__global__ void zero_cnt_kernel(int n_nodes) {
    int i = blockIdx.x * blockDim.x + threadIdx.x;
    if (i < n_nodes) g_cnt[i] = 0;
}

// ---------------------------------------------------------------------------
// 2. bucket fill: int4 dst reads, 4 edges per thread.
// ---------------------------------------------------------------------------
__global__ void fill_kernel(const int4* __restrict__ dst4, int n_edges) {
    int i = blockIdx.x * blockDim.x + threadIdx.x;
    int e0 = i * 4;
    if (e0 + 4 <= n_edges) {
        int4 d = __ldg(dst4 + i);
        int p0 = atomicAdd(&g_cnt[d.x], 1);
        int p1 = atomicAdd(&g_cnt[d.y], 1);
        int p2 = atomicAdd(&g_cnt[d.z], 1);
        int p3 = atomicAdd(&g_cnt[d.w], 1);
        if (p0 < CAP) g_eidx[(size_t)d.x * CAP + p0] = e0;
        if (p1 < CAP) g_eidx[(size_t)d.y * CAP + p1] = e0 + 1;
        if (p2 < CAP) g_eidx[(size_t)d.z * CAP + p2] = e0 + 2;
        if (p3 < CAP) g_eidx[(size_t)d.w * CAP + p3] = e0 + 3;
    } else if (e0 < n_edges) {
        const int* dst = (const int*)dst4;
        for (int e = e0; e < n_edges; e++) {
            int d = __ldg(dst + e);
            int p = atomicAdd(&g_cnt[d], 1);
            if (p < CAP) g_eidx[(size_t)d * CAP + p] = e;
        }
    }
}

// ---------------------------------------------------------------------------
// 3. gather: one warp per node (unchanged from round 9).
// ---------------------------------------------------------------------------
__global__ __launch_bounds__(128)
void gather_kernel(const float4* __restrict__ e4, int n_nodes) {
    int w    = (blockIdx.x * blockDim.x + threadIdx.x) >> 5;
    int lane = threadIdx.x & 31;
    if (w >= n_nodes) return;

    int deg  = g_cnt[w];
    const int* base = g_eidx + (size_t)w * CAP;
    int half = lane >> 4;
    int l16  = lane & 15;

    float ax = 0.f, ay = 0.f, az = 0.f, aw = 0.f;
    int j = 0;
    for (; j + 16 <= deg; j += 16) {
        int e0 = __ldg(base + j + 0  + half);
        int e1 = __ldg(base + j + 2  + half);
        int e2 = __ldg(base + j + 4  + half);
        int e3 = __ldg(base + j + 6  + half);
        int e4i = __ldg(base + j + 8  + half);
        int e5 = __ldg(base + j + 10 + half);
        int e6 = __ldg(base + j + 12 + half);
        int e7 = __ldg(base + j + 14 + half);
        float4 v0 = e4[(size_t)e0 * 16 + l16];
        float4 v1 = e4[(size_t)e1 * 16 + l16];
        float4 v2 = e4[(size_t)e2 * 16 + l16];
        float4 v3 = e4[(size_t)e3 * 16 + l16];
        float4 v4 = e4[(size_t)e4i * 16 + l16];
        float4 v5 = e4[(size_t)e5 * 16 + l16];
        float4 v6 = e4[(size_t)e6 * 16 + l16];
        float4 v7 = e4[(size_t)e7 * 16 + l16];
        ax += ((v0.x + v1.x) + (v2.x + v3.x)) + ((v4.x + v5.x) + (v6.x + v7.x));
        ay += ((v0.y + v1.y) + (v2.y + v3.y)) + ((v4.y + v5.y) + (v6.y + v7.y));
        az += ((v0.z + v1.z) + (v2.z + v3.z)) + ((v4.z + v5.z) + (v6.z + v7.z));
        aw += ((v0.w + v1.w) + (v2.w + v3.w)) + ((v4.w + v5.w) + (v6.w + v7.w));
    }
    if (j + 8 <= deg) {
        int e0 = __ldg(base + j + 0 + half);
        int e1 = __ldg(base + j + 2 + half);
        int e2 = __ldg(base + j + 4 + half);
        int e3 = __ldg(base + j + 6 + half);
        float4 v0 = e4[(size_t)e0 * 16 + l16];
        float4 v1 = e4[(size_t)e1 * 16 + l16];
        float4 v2 = e4[(size_t)e2 * 16 + l16];
        float4 v3 = e4[(size_t)e3 * 16 + l16];
        ax += (v0.x + v1.x) + (v2.x + v3.x);
        ay += (v0.y + v1.y) + (v2.y + v3.y);
        az += (v0.z + v1.z) + (v2.z + v3.z);
        aw += (v0.w + v1.w) + (v2.w + v3.w);
        j += 8;
    }
    if (j + 4 <= deg) {
        int e0 = __ldg(base + j + 0 + half);
        int e1 = __ldg(base + j + 2 + half);
        float4 v0 = e4[(size_t)e0 * 16 + l16];
        float4 v1 = e4[(size_t)e1 * 16 + l16];
        ax += v0.x + v1.x;
        ay += v0.y + v1.y;
        az += v0.z + v1.z;
        aw += v0.w + v1.w;
        j += 4;
    }
    if (j + 2 <= deg) {
        int e0 = __ldg(base + j + half);
        float4 v = e4[(size_t)e0 * 16 + l16];
        ax += v.x; ay += v.y; az += v.z; aw += v.w;
        j += 2;
    }
    if (j < deg && half == 0) {
        int e0 = __ldg(base + j);
        float4 v = e4[(size_t)e0 * 16 + l16];
        ax += v.x; ay += v.y; az += v.z; aw += v.w;
    }

    ax += __shfl_xor_sync(0xffffffffu, ax, 16);
    ay += __shfl_xor_sync(0xffffffffu, ay, 16);
    az += __shfl_xor_sync(0xffffffffu, az, 16);
    aw += __shfl_xor_sync(0xffffffffu, aw, 16);

    if (half == 0)
        reinterpret_cast<float4*>(g_S)[(size_t)w * 16 + l16] =
            make_float4(ax, ay, az, aw);
}

// ---------------------------------------------------------------------------
// 4. GEMM with packed FFMA2 over node pairs.
//    SsmT transposed [k][node], stride 66 (even -> aligned LDS.64 node-pairs).
//    Per k: 5 w-LDS + 5 dup-packs + 4 s-LDS.64 + 20 fma.rn.f32x2.
// ---------------------------------------------------------------------------
#define NT   64
#define NG   8
#define OG   20
#define TPB  (NG * OG)   // 160
#define ST   66          // SsmT row stride (even -> 8B alignment every row)

__global__ __launch_bounds__(TPB)
void gemm_kernel(const float* __restrict__ W,
                 const float* __restrict__ b,
                 float* __restrict__ out,
                 int n_nodes) {
    __shared__ float SsmT[IN_F * ST];       // 16.9 KB  [k][node]
    __shared__ float Wsm[IN_F * OUT_F];     // 25.6 KB  [k][o]
    __shared__ float bsm[OUT_F];
    __shared__ float invd[NT];
    __shared__ float bfac[NT];

    int tid   = threadIdx.x;
    int node0 = blockIdx.x * NT;

    for (int i = tid; i < IN_F * OUT_F; i += TPB) {
        int o = i / IN_F, k = i % IN_F;
        Wsm[k * OUT_F + o] = W[i];
    }
    for (int i = tid; i < OUT_F; i += TPB) bsm[i] = b[i];

    // transposed S tile load: g_S[node][k] -> SsmT[k][node]
    for (int i = tid; i < NT * 16; i += TPB) {
        int r = i >> 4, c = i & 15;          // node r, float4 chunk c
        int node = node0 + r;
        float4 v = make_float4(0.f, 0.f, 0.f, 0.f);
        if (node < n_nodes)
            v = reinterpret_cast<const float4*>(g_S)[(size_t)node * 16 + c];
        SsmT[(c * 4 + 0) * ST + r] = v.x;
        SsmT[(c * 4 + 1) * ST + r] = v.y;
        SsmT[(c * 4 + 2) * ST + r] = v.z;
        SsmT[(c * 4 + 3) * ST + r] = v.w;
    }

    for (int i = tid; i < NT; i += TPB) {
        int node = node0 + i;
        int dg = (node < n_nodes) ? g_cnt[node] : 0;
        invd[i] = (dg > 0) ? (1.0f / (float)dg) : 0.0f;
        bfac[i] = (dg > 0) ? 1.0f : 0.0f;
    }
    __syncthreads();

    int og = tid % OG;   // outs [og*5, og*5+5)
    int ng = tid / OG;   // nodes [ng*8, ng*8+8) as 4 pairs

    unsigned long long acc[4][5];
#pragma unroll
    for (int p = 0; p < 4; p++)
#pragma unroll
        for (int i = 0; i < 5; i++) acc[p][i] = 0ull;

    const float* wp = &Wsm[og * 5];
    const float* sp = &SsmT[ng * 8];

#pragma unroll 4
    for (int k = 0; k < IN_F; k++) {
        unsigned long long w0 = dup2(wp[k * OUT_F + 0]);
        unsigned long long w1 = dup2(wp[k * OUT_F + 1]);
        unsigned long long w2 = dup2(wp[k * OUT_F + 2]);
        unsigned long long w3 = dup2(wp[k * OUT_F + 3]);
        unsigned long long w4 = dup2(wp[k * OUT_F + 4]);
        const unsigned long long* srow =
            reinterpret_cast<const unsigned long long*>(&sp[k * ST]);
#pragma unroll
        for (int p = 0; p < 4; p++) {
            unsigned long long s2 = srow[p];     // nodes (2p, 2p+1)
            fma2(acc[p][0], s2, w0);
            fma2(acc[p][1], s2, w1);
            fma2(acc[p][2], s2, w2);
            fma2(acc[p][3], s2, w3);
            fma2(acc[p][4], s2, w4);
        }
    }

    // writeback: unpack node pairs, scale by 1/deg, add masked bias
#pragma unroll
    for (int p = 0; p < 4; p++) {
        int lrA = ng * 8 + 2 * p;
        int lrB = lrA + 1;
        int nodeA = node0 + lrA;
        int nodeB = node0 + lrB;
        float invA = invd[lrA], bfA = bfac[lrA];
        float invB = invd[lrB], bfB = bfac[lrB];
        float lo, hi;
#pragma unroll
        for (int i = 0; i < 5; i++) {
            unpack2(lo, hi, acc[p][i]);
            float bias = bsm[og * 5 + i];
            if (nodeA < n_nodes)
                out[(size_t)nodeA * OUT_F + og * 5 + i] = lo * invA + bias * bfA;
            if (nodeB < n_nodes)
                out[(size_t)nodeB * OUT_F + og * 5 + i] = hi * invB + bias * bfB;
        }
    }
}

// ---------------------------------------------------------------------------
extern "C" void kernel_launch(void* const* d_in, const int* in_sizes, int n_in,
                              void* d_out, int out_size) {
    const float* e   = (const float*)d_in[0];
    const int*   dst = (const int*)d_in[1];
    const float* W   = (const float*)d_in[2];
    const float* b   = (const float*)d_in[3];
    float*       out = (float*)d_out;

    int n_edges = in_sizes[1];
    int n_nodes = out_size / OUT_F;

    zero_cnt_kernel<<<(n_nodes + 255) / 256, 256>>>(n_nodes);
    int fthreads = (n_edges + 3) / 4;
    fill_kernel<<<(fthreads + 255) / 256, 256>>>((const int4*)dst, n_edges);
    gather_kernel<<<(n_nodes * 32 + 127) / 128, 128>>>((const float4*)e, n_nodes);
    gemm_kernel<<<(n_nodes + NT - 1) / NT, TPB>>>(W, b, out, n_nodes);
}